// round 15
// baseline (speedup 1.0000x reference)
#include <cuda_runtime.h>
#include <cstdint>

// ============================================================================
// out[M,N] = Sx*Sy * (x+66) @ (y-160),  M=N=K=4096, fp32 int-valued inputs.
// Exact int8 decomposition:
//   (x+66)@(y-160) = x@(y-128) - 32*rowsum(x)[m] + 66*colsum(y-128)[n] - 66*32*K
// R15: identical resubmit of R14 (container infra failed twice; no kernel
// signal). R14 = race fix: R11 fused colB-zeroing (x-partition) with colB
// atomicAdds (y-partition) in ONE launch -> unordered -> rel_err jumped
// 1.28e-7 -> 3.8e-4 (nondeterministic, could exceed 1e-3 on another replay).
// Fix: dedicated zero kernel BEFORE the fused convert; stream order in the
// captured graph guarantees zero -> atomicAdd -> gemm-read.
// GEMM frozen at the proven ceiling (948us, tensor=91.5%).
// ============================================================================
constexpr int MD = 4096, ND = 4096, KD = 4096;

constexpr int BM = 128, BN = 128, BK = 64;
constexpr int STAGES = 4;
constexpr int NIT = KD / BK;                    // 64
constexpr int ROW_STRIDE = 80;                  // 64B data + 16B pad: conflict-free LDS
constexpr int STAGE_A = BM * ROW_STRIDE;        // 10240 B
constexpr int STAGE_BYTES = 2 * STAGE_A;        // 20480 B (A tile + B tile)
constexpr int SMEM_TOTAL = STAGES * STAGE_BYTES;  // 81920 B -> 1 CTA/SM
constexpr int CORR_CONST = -66 * 32 * KD;       // -8650752

constexpr int XBLOCKS = MD;                     // 4096 row-blocks for x
constexpr int YBLK_X = ND / 32;                 // 128
constexpr int YBLK   = (ND / 32) * (KD / 32);   // 16384 tile-blocks for y

// Scratch (device globals: allocation-free rule)
__device__ int8_t g_A [(size_t)MD * KD];        // x as int8, [M,K]
__device__ int8_t g_BT[(size_t)ND * KD];        // (y-128) as int8, transposed [N,K]
__device__ int    g_rowA[MD];                   // sum_k x[m,k]
__device__ int    g_colB[ND];                   // sum_k (y[k,n]-128)

// ============================================================================
// Helpers
// ============================================================================
__device__ __forceinline__ void cp_async16(uint32_t dst, const void* src) {
    asm volatile("cp.async.cg.shared.global [%0], [%1], 16;"
                 :: "r"(dst), "l"(src) : "memory");
}

__device__ __forceinline__ uint32_t smem_to_u32(const void* p) {
    uint32_t a;
    asm("{ .reg .u64 t; cvta.to.shared.u64 t, %1; cvt.u32.u64 %0, t; }"
        : "=r"(a) : "l"(p));
    return a;
}

// m16n8k32 s8*s8+s32, A row-major frag, B col-major frag
__device__ __forceinline__ void mma_s8(int* c, const uint32_t* a, const uint32_t* b) {
    asm volatile(
        "mma.sync.aligned.m16n8k32.row.col.s32.s8.s8.s32 "
        "{%0,%1,%2,%3}, {%4,%5,%6,%7}, {%8,%9}, {%0,%1,%2,%3};"
        : "+r"(c[0]), "+r"(c[1]), "+r"(c[2]), "+r"(c[3])
        : "r"(a[0]), "r"(a[1]), "r"(a[2]), "r"(a[3]), "r"(b[0]), "r"(b[1]));
}

// ============================================================================
// Pre-pass 0: zero the colB accumulator. MUST be a separate launch so the
// y-partition atomicAdds in convert_fused are ordered after every zero.
// ============================================================================
__global__ void zero_colB_kernel() {
    int i = blockIdx.x * blockDim.x + threadIdx.x;   // 8 x 512 = 4096
    g_colB[i] = 0;
}

// ============================================================================
// Fused pre-pass: one launch, partitioned grid.
//   blocks [0, XBLOCKS):            x fp32 -> int8 g_A + row sums
//   blocks [XBLOCKS, XBLOCKS+YBLK): y fp32 -> int8 (y-128) transposed g_BT
//                                   + column-sum atomics (colB pre-zeroed)
// ============================================================================
__global__ void __launch_bounds__(256)
convert_fused_kernel(const float* __restrict__ x, const float* __restrict__ y) {
    int tid = threadIdx.x;

    if (blockIdx.x < XBLOCKS) {
        // ---- x partition: one block per row ----
        int m = blockIdx.x;
        const float4* xr = reinterpret_cast<const float4*>(x + (size_t)m * KD);
        char4* ar = reinterpret_cast<char4*>(g_A + (size_t)m * KD);
        int partial = 0;
#pragma unroll
        for (int j = 0; j < 4; j++) {
            int i = j * 256 + tid;              // 1024 float4 per row
            float4 v = xr[i];
            int i0 = __float2int_rn(v.x), i1 = __float2int_rn(v.y);
            int i2 = __float2int_rn(v.z), i3 = __float2int_rn(v.w);
            partial += i0 + i1 + i2 + i3;
            ar[i] = make_char4((char)i0, (char)i1, (char)i2, (char)i3);
        }
#pragma unroll
        for (int o = 16; o > 0; o >>= 1)
            partial += __shfl_xor_sync(0xFFFFFFFFu, partial, o);
        __shared__ int ws[8];
        if ((tid & 31) == 0) ws[tid >> 5] = partial;
        __syncthreads();
        if (tid == 0) {
            int s = 0;
#pragma unroll
            for (int w = 0; w < 8; w++) s += ws[w];
            g_rowA[m] = s;
        }
    } else {
        // ---- y partition: one block per 32x32 tile ----
        int yb = blockIdx.x - XBLOCKS;
        int n0 = (yb % YBLK_X) * 32, k0 = (yb / YBLK_X) * 32;
        int tx = tid & 31, ty = tid >> 5;       // logical (32, 8)

        __shared__ int8_t t[32][36];            // t[n_local][k_local], 36B pad
        __shared__ int cs[8][32];
        int colPart = 0;                        // partial sum, column n0+tx
#pragma unroll
        for (int j = 0; j < 32; j += 8) {
            int v = __float2int_rn(y[(size_t)(k0 + ty + j) * ND + n0 + tx]) - 128;
            t[tx][ty + j] = (int8_t)v;          // store pre-transposed
            colPart += v;
        }
        cs[ty][tx] = colPart;
        __syncthreads();
        // Output: flat thread -> row nn (0..31), 4B k-chunk kc. One aligned
        // 4-byte SMEM word load, one 4B global store of contiguous K.
        {
            int nn = tid >> 3;                  // 32 rows
            int kc = (tid & 7) * 4;             // 8 chunks of 4 K-bytes
            uint32_t w = *reinterpret_cast<const uint32_t*>(&t[nn][kc]);
            *reinterpret_cast<uint32_t*>(&g_BT[(size_t)(n0 + nn) * KD + k0 + kc]) = w;
        }
        if (ty == 0) {
            int s = 0;
#pragma unroll
            for (int w = 0; w < 8; w++) s += cs[w][tx];
            atomicAdd(&g_colB[n0 + tx], s);
        }
    }
}

// ============================================================================
// GEMM: 128x128 tile, 256 threads (2x4 warps, 64x32 warp tiles),
// 4-stage cp.async pipeline (BK=64), single barrier per iteration,
// batched fragment loads, m16n8k32 s8 IMMA, int-exact epilogue. 1 CTA/SM.
// IDENTICAL to R8/R10 (proven best -- do not touch).
// ============================================================================
__device__ __forceinline__ void fill_stage(uint32_t smemBase, int stage,
                                           const int8_t* gA, const int8_t* gB,
                                           int kIter, int tid) {
    uint32_t aBase = smemBase + stage * STAGE_BYTES;
    uint32_t bBase = aBase + STAGE_A;
    int k0 = kIter * BK;
#pragma unroll
    for (int i = 0; i < 2; i++) {
        int c = tid + i * 256;          // 0..511: 16B chunks (128 rows x 4)
        int row = c >> 2;
        int col = (c & 3) * 16;
        cp_async16(aBase + row * ROW_STRIDE + col, gA + (size_t)row * KD + k0 + col);
        cp_async16(bBase + row * ROW_STRIDE + col, gB + (size_t)row * KD + k0 + col);
    }
}

__global__ void __launch_bounds__(256, 1)
gemm_kernel(float* __restrict__ out) {
    extern __shared__ int8_t smem[];
    uint32_t smemBase = smem_to_u32(smem);
    int tid = threadIdx.x, lane = tid & 31, warp = tid >> 5;
    int warpM = warp >> 2, warpN = warp & 3;    // 2 x 4 warp grid
    int tileM = blockIdx.x, tileN = blockIdx.y;

    const int8_t* gA = g_A  + (size_t)tileM * BM * KD;
    const int8_t* gB = g_BT + (size_t)tileN * BN * KD;

    int acc[4][4][4];                           // [mfrag][nfrag][c0..c3]
#pragma unroll
    for (int i = 0; i < 4; i++)
#pragma unroll
        for (int j = 0; j < 4; j++)
#pragma unroll
            for (int k = 0; k < 4; k++) acc[i][j][k] = 0;

    // Prologue: stages 0..2 (groups g0..g2)
#pragma unroll
    for (int s = 0; s < STAGES - 1; s++) {
        fill_stage(smemBase, s, gA, gB, s, tid);
        asm volatile("cp.async.commit_group;" ::: "memory");
    }

    int laneRow = lane >> 2;        // 0..7
    int laneCol4 = (lane & 3) * 4;  // byte offset within k-group

    for (int it = 0; it < NIT; it++) {
        // Pending = {g_it, g_it+1, g_it+2}; wait_group 2 completes exactly g_it.
        asm volatile("cp.async.wait_group %0;" :: "n"(STAGES - 2) : "memory");
        // Single barrier: publishes stage `it` data AND proves all warps
        // finished reading stage (it+3)&3 (consumed at it-1) before the
        // fill below overwrites it.
        __syncthreads();

        if (it + STAGES - 1 < NIT)
            fill_stage(smemBase, (it + STAGES - 1) & (STAGES - 1), gA, gB,
                       it + STAGES - 1, tid);
        asm volatile("cp.async.commit_group;" ::: "memory");  // unconditional

        const int8_t* sa = smem + (it & (STAGES - 1)) * STAGE_BYTES;
        const int8_t* sb = sa + STAGE_A;

        // Batch ALL fragment loads for both k32 steps (48 LDS), then MMA.
        uint32_t a[2][4][4], b[2][4][2];
#pragma unroll
        for (int ks = 0; ks < 2; ks++) {
            int kb = ks * 32;
#pragma unroll
            for (int mf = 0; mf < 4; mf++) {
                int rlo = warpM * 64 + mf * 16 + laneRow;
                const int8_t* pLo = sa + rlo * ROW_STRIDE + kb + laneCol4;
                const int8_t* pHi = pLo + 8 * ROW_STRIDE;
                a[ks][mf][0] = *reinterpret_cast<const uint32_t*>(pLo);
                a[ks][mf][1] = *reinterpret_cast<const uint32_t*>(pHi);
                a[ks][mf][2] = *reinterpret_cast<const uint32_t*>(pLo + 16);
                a[ks][mf][3] = *reinterpret_cast<const uint32_t*>(pHi + 16);
            }
#pragma unroll
            for (int nf = 0; nf < 4; nf++) {
                int n = warpN * 32 + nf * 8 + laneRow;
                const int8_t* p = sb + n * ROW_STRIDE + kb + laneCol4;
                b[ks][nf][0] = *reinterpret_cast<const uint32_t*>(p);
                b[ks][nf][1] = *reinterpret_cast<const uint32_t*>(p + 16);
            }
        }
#pragma unroll
        for (int ks = 0; ks < 2; ks++)
#pragma unroll
            for (int mf = 0; mf < 4; mf++)
#pragma unroll
                for (int nf = 0; nf < 4; nf++)
                    mma_s8(acc[mf][nf], a[ks][mf], b[ks][nf]);
    }

    // ------------------------------------------------------------------------
    // Epilogue: out = S * (dot - 32*rowA[m] + 66*colB[n] + CORR_CONST)
    // float2 stores (c0,c1 are contiguous columns).
    // ------------------------------------------------------------------------
    const float S = 0.03f * 0.025f;
    int mBase = tileM * BM + warpM * 64;
    int nBase = tileN * BN + warpN * 32;
#pragma unroll
    for (int nf = 0; nf < 4; nf++) {
        int col = nBase + nf * 8 + 2 * (lane & 3);
        int cb0 = 66 * g_colB[col]     + CORR_CONST;
        int cb1 = 66 * g_colB[col + 1] + CORR_CONST;
#pragma unroll
        for (int mf = 0; mf < 4; mf++) {
            int rlo = mBase + mf * 16 + laneRow;
            int rhi = rlo + 8;
            int cmLo = -32 * g_rowA[rlo];
            int cmHi = -32 * g_rowA[rhi];
            float2 vLo = make_float2(S * (float)(acc[mf][nf][0] + cmLo + cb0),
                                     S * (float)(acc[mf][nf][1] + cmLo + cb1));
            float2 vHi = make_float2(S * (float)(acc[mf][nf][2] + cmHi + cb0),
                                     S * (float)(acc[mf][nf][3] + cmHi + cb1));
            *reinterpret_cast<float2*>(out + (size_t)rlo * ND + col) = vLo;
            *reinterpret_cast<float2*>(out + (size_t)rhi * ND + col) = vHi;
        }
    }
}

// ============================================================================
// kernel_launch
// ============================================================================
extern "C" void kernel_launch(void* const* d_in, const int* in_sizes, int n_in,
                              void* d_out, int out_size) {
    const float* x = (const float*)d_in[0];     // [M,K]
    const float* y = (const float*)d_in[1];     // [K,N]
    float* out = (float*)d_out;                 // [M,N]

    cudaFuncSetAttribute(gemm_kernel,
                         cudaFuncAttributeMaxDynamicSharedMemorySize,
                         SMEM_TOTAL);

    zero_colB_kernel<<<8, 512>>>();             // ordered before the atomics
    convert_fused_kernel<<<XBLOCKS + YBLK, 256>>>(x, y);
    {
        dim3 grid(MD / BM, ND / BN);
        gemm_kernel<<<grid, 256, SMEM_TOTAL>>>(out);
    }
}

// round 16
// speedup vs baseline: 1.0047x; 1.0047x over previous
#include <cuda_runtime.h>
#include <cstdint>

// ============================================================================
// out[M,N] = Sx*Sy * (x+66) @ (y-160),  M=N=K=4096, fp32 int-valued inputs.
// Exact int8 decomposition:
//   (x+66)@(y-160) = x@(y-128) - 32*rowsum(x)[m] + 66*colsum(y-128)[n] - 66*32*K
// R16: R15 (986us, rel_err 1.276e-7, race-free) + y-partition tiles enlarged
// 32x32 -> 64x64: y-block count 16384 -> 4096 (amortize per-block fixed cost,
// the identified ~9us convert slop) and output becomes one uint4 store per
// thread. GEMM and ordering (zero -> atomicAdd -> read) byte-frozen.
// ============================================================================
constexpr int MD = 4096, ND = 4096, KD = 4096;

constexpr int BM = 128, BN = 128, BK = 64;
constexpr int STAGES = 4;
constexpr int NIT = KD / BK;                    // 64
constexpr int ROW_STRIDE = 80;                  // 64B data + 16B pad: conflict-free LDS
constexpr int STAGE_A = BM * ROW_STRIDE;        // 10240 B
constexpr int STAGE_BYTES = 2 * STAGE_A;        // 20480 B (A tile + B tile)
constexpr int SMEM_TOTAL = STAGES * STAGE_BYTES;  // 81920 B -> 1 CTA/SM
constexpr int CORR_CONST = -66 * 32 * KD;       // -8650752

constexpr int XBLOCKS = MD;                     // 4096 row-blocks for x
constexpr int YT = 64;                          // y tile edge
constexpr int YBLK_X = ND / YT;                 // 64
constexpr int YBLK   = (ND / YT) * (KD / YT);   // 4096 tile-blocks for y

// Scratch (device globals: allocation-free rule)
__device__ int8_t g_A [(size_t)MD * KD];        // x as int8, [M,K]
__device__ int8_t g_BT[(size_t)ND * KD];        // (y-128) as int8, transposed [N,K]
__device__ int    g_rowA[MD];                   // sum_k x[m,k]
__device__ int    g_colB[ND];                   // sum_k (y[k,n]-128)

// ============================================================================
// Helpers
// ============================================================================
__device__ __forceinline__ void cp_async16(uint32_t dst, const void* src) {
    asm volatile("cp.async.cg.shared.global [%0], [%1], 16;"
                 :: "r"(dst), "l"(src) : "memory");
}

__device__ __forceinline__ uint32_t smem_to_u32(const void* p) {
    uint32_t a;
    asm("{ .reg .u64 t; cvta.to.shared.u64 t, %1; cvt.u32.u64 %0, t; }"
        : "=r"(a) : "l"(p));
    return a;
}

// m16n8k32 s8*s8+s32, A row-major frag, B col-major frag
__device__ __forceinline__ void mma_s8(int* c, const uint32_t* a, const uint32_t* b) {
    asm volatile(
        "mma.sync.aligned.m16n8k32.row.col.s32.s8.s8.s32 "
        "{%0,%1,%2,%3}, {%4,%5,%6,%7}, {%8,%9}, {%0,%1,%2,%3};"
        : "+r"(c[0]), "+r"(c[1]), "+r"(c[2]), "+r"(c[3])
        : "r"(a[0]), "r"(a[1]), "r"(a[2]), "r"(a[3]), "r"(b[0]), "r"(b[1]));
}

// ============================================================================
// Pre-pass 0: zero the colB accumulator. Separate launch -> stream order
// guarantees every zero lands before any y-partition atomicAdd.
// ============================================================================
__global__ void zero_colB_kernel() {
    int i = blockIdx.x * blockDim.x + threadIdx.x;   // 8 x 512 = 4096
    g_colB[i] = 0;
}

// ============================================================================
// Fused pre-pass: one launch, partitioned grid.
//   blocks [0, XBLOCKS):            x fp32 -> int8 g_A + row sums
//   blocks [XBLOCKS, XBLOCKS+YBLK): y fp32 -> int8 (y-128) transposed g_BT
//                                   (64x64 tiles) + column-sum atomics
// ============================================================================
__global__ void __launch_bounds__(256)
convert_fused_kernel(const float* __restrict__ x, const float* __restrict__ y) {
    int tid = threadIdx.x;

    if (blockIdx.x < XBLOCKS) {
        // ---- x partition: one block per row ----
        int m = blockIdx.x;
        const float4* xr = reinterpret_cast<const float4*>(x + (size_t)m * KD);
        char4* ar = reinterpret_cast<char4*>(g_A + (size_t)m * KD);
        int partial = 0;
#pragma unroll
        for (int j = 0; j < 4; j++) {
            int i = j * 256 + tid;              // 1024 float4 per row
            float4 v = xr[i];
            int i0 = __float2int_rn(v.x), i1 = __float2int_rn(v.y);
            int i2 = __float2int_rn(v.z), i3 = __float2int_rn(v.w);
            partial += i0 + i1 + i2 + i3;
            ar[i] = make_char4((char)i0, (char)i1, (char)i2, (char)i3);
        }
#pragma unroll
        for (int o = 16; o > 0; o >>= 1)
            partial += __shfl_xor_sync(0xFFFFFFFFu, partial, o);
        __shared__ int ws[8];
        if ((tid & 31) == 0) ws[tid >> 5] = partial;
        __syncthreads();
        if (tid == 0) {
            int s = 0;
#pragma unroll
            for (int w = 0; w < 8; w++) s += ws[w];
            g_rowA[m] = s;
        }
    } else {
        // ---- y partition: one block per 64x64 tile ----
        int yb = blockIdx.x - XBLOCKS;
        int n0 = (yb & (YBLK_X - 1)) * YT;
        int k0 = (yb / YBLK_X) * YT;
        int tx = tid & 63, ty = tid >> 6;       // logical (64, 4)

        __shared__ int8_t t[64][68];            // t[n_local][k_local], 68B pad
        __shared__ int cs[4][64];
        int colPart = 0;                        // partial sum, column n0+tx
#pragma unroll
        for (int j = 0; j < 64; j += 4) {
            int v = __float2int_rn(y[(size_t)(k0 + ty + j) * ND + n0 + tx]) - 128;
            t[tx][ty + j] = (int8_t)v;          // store pre-transposed
            colPart += v;
        }
        cs[ty][tx] = colPart;
        __syncthreads();
        // Output: thread -> row nn (0..63), 16B k-chunk kc (0/16/32/48).
        // Four aligned 4B SMEM word loads -> one uint4 global store.
        {
            int nn = tid >> 2;
            int kc = (tid & 3) * 16;
            const uint32_t* tw = reinterpret_cast<const uint32_t*>(&t[nn][kc]);
            uint4 w4 = make_uint4(tw[0], tw[1], tw[2], tw[3]);
            *reinterpret_cast<uint4*>(&g_BT[(size_t)(n0 + nn) * KD + k0 + kc]) = w4;
        }
        if (tid < 64) {
            int s = cs[0][tid] + cs[1][tid] + cs[2][tid] + cs[3][tid];
            atomicAdd(&g_colB[n0 + tid], s);
        }
    }
}

// ============================================================================
// GEMM: 128x128 tile, 256 threads (2x4 warps, 64x32 warp tiles),
// 4-stage cp.async pipeline (BK=64), single barrier per iteration,
// batched fragment loads, m16n8k32 s8 IMMA, int-exact epilogue. 1 CTA/SM.
// IDENTICAL to R8/R10/R15 (proven best -- do not touch).
// ============================================================================
__device__ __forceinline__ void fill_stage(uint32_t smemBase, int stage,
                                           const int8_t* gA, const int8_t* gB,
                                           int kIter, int tid) {
    uint32_t aBase = smemBase + stage * STAGE_BYTES;
    uint32_t bBase = aBase + STAGE_A;
    int k0 = kIter * BK;
#pragma unroll
    for (int i = 0; i < 2; i++) {
        int c = tid + i * 256;          // 0..511: 16B chunks (128 rows x 4)
        int row = c >> 2;
        int col = (c & 3) * 16;
        cp_async16(aBase + row * ROW_STRIDE + col, gA + (size_t)row * KD + k0 + col);
        cp_async16(bBase + row * ROW_STRIDE + col, gB + (size_t)row * KD + k0 + col);
    }
}

__global__ void __launch_bounds__(256, 1)
gemm_kernel(float* __restrict__ out) {
    extern __shared__ int8_t smem[];
    uint32_t smemBase = smem_to_u32(smem);
    int tid = threadIdx.x, lane = tid & 31, warp = tid >> 5;
    int warpM = warp >> 2, warpN = warp & 3;    // 2 x 4 warp grid
    int tileM = blockIdx.x, tileN = blockIdx.y;

    const int8_t* gA = g_A  + (size_t)tileM * BM * KD;
    const int8_t* gB = g_BT + (size_t)tileN * BN * KD;

    int acc[4][4][4];                           // [mfrag][nfrag][c0..c3]
#pragma unroll
    for (int i = 0; i < 4; i++)
#pragma unroll
        for (int j = 0; j < 4; j++)
#pragma unroll
            for (int k = 0; k < 4; k++) acc[i][j][k] = 0;

    // Prologue: stages 0..2 (groups g0..g2)
#pragma unroll
    for (int s = 0; s < STAGES - 1; s++) {
        fill_stage(smemBase, s, gA, gB, s, tid);
        asm volatile("cp.async.commit_group;" ::: "memory");
    }

    int laneRow = lane >> 2;        // 0..7
    int laneCol4 = (lane & 3) * 4;  // byte offset within k-group

    for (int it = 0; it < NIT; it++) {
        // Pending = {g_it, g_it+1, g_it+2}; wait_group 2 completes exactly g_it.
        asm volatile("cp.async.wait_group %0;" :: "n"(STAGES - 2) : "memory");
        // Single barrier: publishes stage `it` data AND proves all warps
        // finished reading stage (it+3)&3 (consumed at it-1) before the
        // fill below overwrites it.
        __syncthreads();

        if (it + STAGES - 1 < NIT)
            fill_stage(smemBase, (it + STAGES - 1) & (STAGES - 1), gA, gB,
                       it + STAGES - 1, tid);
        asm volatile("cp.async.commit_group;" ::: "memory");  // unconditional

        const int8_t* sa = smem + (it & (STAGES - 1)) * STAGE_BYTES;
        const int8_t* sb = sa + STAGE_A;

        // Batch ALL fragment loads for both k32 steps (48 LDS), then MMA.
        uint32_t a[2][4][4], b[2][4][2];
#pragma unroll
        for (int ks = 0; ks < 2; ks++) {
            int kb = ks * 32;
#pragma unroll
            for (int mf = 0; mf < 4; mf++) {
                int rlo = warpM * 64 + mf * 16 + laneRow;
                const int8_t* pLo = sa + rlo * ROW_STRIDE + kb + laneCol4;
                const int8_t* pHi = pLo + 8 * ROW_STRIDE;
                a[ks][mf][0] = *reinterpret_cast<const uint32_t*>(pLo);
                a[ks][mf][1] = *reinterpret_cast<const uint32_t*>(pHi);
                a[ks][mf][2] = *reinterpret_cast<const uint32_t*>(pLo + 16);
                a[ks][mf][3] = *reinterpret_cast<const uint32_t*>(pHi + 16);
            }
#pragma unroll
            for (int nf = 0; nf < 4; nf++) {
                int n = warpN * 32 + nf * 8 + laneRow;
                const int8_t* p = sb + n * ROW_STRIDE + kb + laneCol4;
                b[ks][nf][0] = *reinterpret_cast<const uint32_t*>(p);
                b[ks][nf][1] = *reinterpret_cast<const uint32_t*>(p + 16);
            }
        }
#pragma unroll
        for (int ks = 0; ks < 2; ks++)
#pragma unroll
            for (int mf = 0; mf < 4; mf++)
#pragma unroll
                for (int nf = 0; nf < 4; nf++)
                    mma_s8(acc[mf][nf], a[ks][mf], b[ks][nf]);
    }

    // ------------------------------------------------------------------------
    // Epilogue: out = S * (dot - 32*rowA[m] + 66*colB[n] + CORR_CONST)
    // float2 stores (c0,c1 are contiguous columns).
    // ------------------------------------------------------------------------
    const float S = 0.03f * 0.025f;
    int mBase = tileM * BM + warpM * 64;
    int nBase = tileN * BN + warpN * 32;
#pragma unroll
    for (int nf = 0; nf < 4; nf++) {
        int col = nBase + nf * 8 + 2 * (lane & 3);
        int cb0 = 66 * g_colB[col]     + CORR_CONST;
        int cb1 = 66 * g_colB[col + 1] + CORR_CONST;
#pragma unroll
        for (int mf = 0; mf < 4; mf++) {
            int rlo = mBase + mf * 16 + laneRow;
            int rhi = rlo + 8;
            int cmLo = -32 * g_rowA[rlo];
            int cmHi = -32 * g_rowA[rhi];
            float2 vLo = make_float2(S * (float)(acc[mf][nf][0] + cmLo + cb0),
                                     S * (float)(acc[mf][nf][1] + cmLo + cb1));
            float2 vHi = make_float2(S * (float)(acc[mf][nf][2] + cmHi + cb0),
                                     S * (float)(acc[mf][nf][3] + cmHi + cb1));
            *reinterpret_cast<float2*>(out + (size_t)rlo * ND + col) = vLo;
            *reinterpret_cast<float2*>(out + (size_t)rhi * ND + col) = vHi;
        }
    }
}

// ============================================================================
// kernel_launch
// ============================================================================
extern "C" void kernel_launch(void* const* d_in, const int* in_sizes, int n_in,
                              void* d_out, int out_size) {
    const float* x = (const float*)d_in[0];     // [M,K]
    const float* y = (const float*)d_in[1];     // [K,N]
    float* out = (float*)d_out;                 // [M,N]

    cudaFuncSetAttribute(gemm_kernel,
                         cudaFuncAttributeMaxDynamicSharedMemorySize,
                         SMEM_TOTAL);

    zero_colB_kernel<<<8, 512>>>();             // ordered before the atomics
    convert_fused_kernel<<<XBLOCKS + YBLK, 256>>>(x, y);
    {
        dim3 grid(MD / BM, ND / BN);
        gemm_kernel<<<grid, 256, SMEM_TOTAL>>>(out);
    }
}